// round 7
// baseline (speedup 1.0000x reference)
#include <cuda_runtime.h>

#define B_N   8
#define H_IN  384
#define W_IN  384
#define HO    382
#define WO    382
#define KST   64
#define NB    9
#define HOWO  (HO * WO)

#define NBLK   1152      // persistent blocks; each does exactly 2 tiles
#define NTILE  2304      // 3 col-slabs x 96 row-groups x 8 batches

// ---- packed f32x2 helpers (Blackwell) ----
__device__ __forceinline__ unsigned long long dup2(float v) {
    unsigned long long r;
    asm("mov.b64 %0, {%1, %1};" : "=l"(r) : "f"(v));
    return r;
}
__device__ __forceinline__ unsigned long long fma2(unsigned long long a,
                                                   unsigned long long b,
                                                   unsigned long long c) {
    unsigned long long d;
    asm("fma.rn.f32x2 %0, %1, %2, %3;" : "=l"(d) : "l"(a), "l"(b), "l"(c));
    return d;
}
__device__ __forceinline__ unsigned long long mul2(unsigned long long a,
                                                   unsigned long long b) {
    unsigned long long d;
    asm("mul.rn.f32x2 %0, %1, %2;" : "=l"(d) : "l"(a), "l"(b));
    return d;
}
__device__ __forceinline__ unsigned long long add2(unsigned long long a,
                                                   unsigned long long b) {
    unsigned long long d;
    asm("add.rn.f32x2 %0, %1, %2;" : "=l"(d) : "l"(a), "l"(b));
    return d;
}
__device__ __forceinline__ void unpack2(unsigned long long d, float& lo, float& hi) {
    asm("mov.b64 {%0, %1}, %2;" : "=f"(lo), "=f"(hi) : "l"(d));
}

// Block: (32, 4) = 128 threads. Grid: 1152 persistent blocks, each handles
// tiles {bid, bid+1152} -> perfectly uniform 2 tiles/block, one resident
// wave (<=8 CTAs/SM), weights staged ONCE per block.
// Tile = (col-slab cx in 0..2, row-group by in 0..95, batch bz in 0..7);
// thread = 4 consecutive output columns of one output row.
//
// Shared sW: per state-pair sp (32 pairs), stride 24 floats (96 B,
// 16B-aligned -> LDS.128 broadcast):
//   [sp*24 + 0..1]       = (b[2sp], b[2sp+1])
//   [sp*24 + 2+2k..3+2k] = (W[k][2sp], W[k][2sp+1])  k = 0..8
__global__ __launch_bounds__(128, 8) void qconv_kernel(
    const float* __restrict__ x, const float* __restrict__ W,
    const float* __restrict__ b, const int* __restrict__ keys,
    float* __restrict__ out)
{
    __shared__ __align__(16) float sW[32 * 24];   // 3072 B
    __shared__ float sKeys[KST * NB];             // 2304 B

    const float c0 = 1.5707963267948966f; // pi/2

    const int tid = threadIdx.y * 32 + threadIdx.x;

    if (tid < KST) {
        const int s = tid;
        const int sp = s >> 1, h = s & 1;
        sW[sp * 24 + h] = b[s];
        #pragma unroll
        for (int k = 0; k < NB; ++k)
            sW[sp * 24 + 2 + 2 * k + h] = W[k * KST + s];
    }
    for (int idx = tid; idx < KST * NB; idx += 128)
        sKeys[idx] = (float)keys[idx];
    __syncthreads();

    for (int tile = blockIdx.x; tile < NTILE; tile += NBLK) {
        const int bz  = tile / 288;          // 288 = 3 * 96
        const int rem = tile - bz * 288;
        const int by  = rem / 3;
        const int cx  = rem - by * 3;

        const int i  = by * 4 + threadIdx.y;
        const int j0 = cx * 128 + threadIdx.x * 4;  // multiple of 4, <= 380
        if (i >= HO) continue;                       // only by==95, ty>=2

        const float* xb = x + bz * (H_IN * W_IN);

        // 3x6 patch block: float4 + predicated float2 per row; transform
        // (v - 0.5f) * pi/2 exactly as the reference; dup into f32x2 lanes.
        unsigned long long P[18];
        const bool tail_ok = (j0 <= W_IN - 6);   // false only for j0 == 380
        #pragma unroll
        for (int r = 0; r < 3; ++r) {
            const float* rp = xb + (i + r) * W_IN + j0;
            float4 v4 = *reinterpret_cast<const float4*>(rp);
            float2 v2 = tail_ok ? *reinterpret_cast<const float2*>(rp + 4)
                                : make_float2(0.f, 0.f);
            float v[6] = { v4.x, v4.y, v4.z, v4.w, v2.x, v2.y };
            #pragma unroll
            for (int c = 0; c < 6; ++c)
                P[r * 6 + c] = dup2((v[c] - 0.5f) * c0);
        }

        float best0 = -3.4e38f, best1 = -3.4e38f,
              best2 = -3.4e38f, best3 = -3.4e38f;
        int   bi0 = 0, bi1 = 0, bi2 = 0, bi3 = 0;

        #pragma unroll 16
        for (int sp = 0; sp < 32; ++sp) {
            const ulonglong2* wp =
                reinterpret_cast<const ulonglong2*>(&sW[sp * 24]);
            const ulonglong2 q0 = wp[0];   // (b_pair, w0)
            const ulonglong2 q1 = wp[1];   // (w1, w2)
            const ulonglong2 q2 = wp[2];   // (w3, w4)
            const ulonglong2 q3 = wp[3];   // (w5, w6)
            const ulonglong2 q4 = wp[4];   // (w7, w8)

            // Bit-identical summation order: (((p0*w0 + p1*w1) + ...) + b)
            unsigned long long a0 = mul2(P[0], q0.y);
            unsigned long long a1 = mul2(P[1], q0.y);
            unsigned long long a2 = mul2(P[2], q0.y);
            unsigned long long a3 = mul2(P[3], q0.y);

            a0 = fma2(P[1],  q1.x, a0);  a1 = fma2(P[2],  q1.x, a1);
            a2 = fma2(P[3],  q1.x, a2);  a3 = fma2(P[4],  q1.x, a3);

            a0 = fma2(P[2],  q1.y, a0);  a1 = fma2(P[3],  q1.y, a1);
            a2 = fma2(P[4],  q1.y, a2);  a3 = fma2(P[5],  q1.y, a3);

            a0 = fma2(P[6],  q2.x, a0);  a1 = fma2(P[7],  q2.x, a1);
            a2 = fma2(P[8],  q2.x, a2);  a3 = fma2(P[9],  q2.x, a3);

            a0 = fma2(P[7],  q2.y, a0);  a1 = fma2(P[8],  q2.y, a1);
            a2 = fma2(P[9],  q2.y, a2);  a3 = fma2(P[10], q2.y, a3);

            a0 = fma2(P[8],  q3.x, a0);  a1 = fma2(P[9],  q3.x, a1);
            a2 = fma2(P[10], q3.x, a2);  a3 = fma2(P[11], q3.x, a3);

            a0 = fma2(P[12], q3.y, a0);  a1 = fma2(P[13], q3.y, a1);
            a2 = fma2(P[14], q3.y, a2);  a3 = fma2(P[15], q3.y, a3);

            a0 = fma2(P[13], q4.x, a0);  a1 = fma2(P[14], q4.x, a1);
            a2 = fma2(P[15], q4.x, a2);  a3 = fma2(P[16], q4.x, a3);

            a0 = fma2(P[14], q4.y, a0);  a1 = fma2(P[15], q4.y, a1);
            a2 = fma2(P[16], q4.y, a2);  a3 = fma2(P[17], q4.y, a3);

            a0 = add2(a0, q0.x);
            a1 = add2(a1, q0.x);
            a2 = add2(a2, q0.x);
            a3 = add2(a3, q0.x);

            // Argmax: pair winner first (independent of best), then one
            // best-dependent compare. Identical to sequential strict-> scan.
            const int s0 = sp * 2;
            float lo, hi;
            {
                unpack2(a0, lo, hi);
                const bool q = hi > lo;
                const float cand = q ? hi : lo;
                const int   ci   = q ? s0 + 1 : s0;
                if (cand > best0) { best0 = cand; bi0 = ci; }
            }
            {
                unpack2(a1, lo, hi);
                const bool q = hi > lo;
                const float cand = q ? hi : lo;
                const int   ci   = q ? s0 + 1 : s0;
                if (cand > best1) { best1 = cand; bi1 = ci; }
            }
            {
                unpack2(a2, lo, hi);
                const bool q = hi > lo;
                const float cand = q ? hi : lo;
                const int   ci   = q ? s0 + 1 : s0;
                if (cand > best2) { best2 = cand; bi2 = ci; }
            }
            {
                unpack2(a3, lo, hi);
                const bool q = hi > lo;
                const float cand = q ? hi : lo;
                const int   ci   = q ? s0 + 1 : s0;
                if (cand > best3) { best3 = cand; bi3 = ci; }
            }
        }

        // Decode + store (int32 addressing; float2 stores, 8B-aligned).
        const int obase = bz * (NB * HOWO) + i * WO + j0;
        const float* kr0 = &sKeys[bi0 * NB];
        const float* kr1 = &sKeys[bi1 * NB];
        const float* kr2 = &sKeys[bi2 * NB];
        const float* kr3 = &sKeys[bi3 * NB];
        const bool hi_ok = (j0 + 3 < WO);
        #pragma unroll
        for (int k = 0; k < NB; ++k) {
            float* op = out + obase + k * HOWO;
            *reinterpret_cast<float2*>(op) = make_float2(kr0[k], kr1[k]);
            if (hi_ok)
                *reinterpret_cast<float2*>(op + 2) = make_float2(kr2[k], kr3[k]);
        }
    }
}

extern "C" void kernel_launch(void* const* d_in, const int* in_sizes, int n_in,
                              void* d_out, int out_size) {
    const float* x    = (const float*)d_in[0];
    const float* W    = (const float*)d_in[1];
    const float* b    = (const float*)d_in[2];
    const int*   keys = (const int*)d_in[3];
    float*       out  = (float*)d_out;

    dim3 block(32, 4);        // 128 threads
    dim3 grid(NBLK);          // 1152 persistent blocks, 2 tiles each
    qconv_kernel<<<grid, block>>>(x, W, b, keys, out);
}

// round 8
// speedup vs baseline: 1.1783x; 1.1783x over previous
#include <cuda_runtime.h>

#define B_N   8
#define H_IN  384
#define W_IN  384
#define HO    382
#define WO    382
#define KST   64
#define NB    9
#define HOWO  (HO * WO)

// Weights and biases live in constant memory, copied device-to-device in
// kernel_launch (graph-capturable). Native layout: cW[k*64 + s], cB[s] --
// adjacent states contiguous, so a state-pair is one 8-byte const load.
__constant__ float cW[NB * KST];   // 2304 B
__constant__ float cB[KST];        // 256 B

// ---- packed f32x2 helpers (Blackwell) ----
__device__ __forceinline__ unsigned long long dup2(float v) {
    unsigned long long r;
    asm("mov.b64 %0, {%1, %1};" : "=l"(r) : "f"(v));
    return r;
}
__device__ __forceinline__ unsigned long long fma2(unsigned long long a,
                                                   unsigned long long b,
                                                   unsigned long long c) {
    unsigned long long d;
    asm("fma.rn.f32x2 %0, %1, %2, %3;" : "=l"(d) : "l"(a), "l"(b), "l"(c));
    return d;
}
__device__ __forceinline__ unsigned long long mul2(unsigned long long a,
                                                   unsigned long long b) {
    unsigned long long d;
    asm("mul.rn.f32x2 %0, %1, %2;" : "=l"(d) : "l"(a), "l"(b));
    return d;
}
__device__ __forceinline__ unsigned long long add2(unsigned long long a,
                                                   unsigned long long b) {
    unsigned long long d;
    asm("add.rn.f32x2 %0, %1, %2;" : "=l"(d) : "l"(a), "l"(b));
    return d;
}
__device__ __forceinline__ void unpack2(unsigned long long d, float& lo, float& hi) {
    asm("mov.b64 {%0, %1}, %2;" : "=f"(lo), "=f"(hi) : "l"(d));
}

__device__ __forceinline__ unsigned long long cpair(const float* p) {
    return *reinterpret_cast<const unsigned long long*>(p);
}

// Block: (32, 4) = 128 threads, <=56 regs -> 9+ CTAs/SM resident.
// Thread = 4 consecutive output columns of one output row.
// Grid: (3 col-slabs of 128, 96 row-groups, 8 batches) = 2304 blocks.
// Weights come from constant memory (uniform loads, off the L1 path);
// only the keys table is staged in shared (per-lane gather at decode).
__global__ __launch_bounds__(128, 9) void qconv_kernel(
    const float* __restrict__ x, const int* __restrict__ keys,
    float* __restrict__ out)
{
    __shared__ float sKeys[KST * NB];   // 2304 B

    const float c0 = 1.5707963267948966f; // pi/2

    const int tid = threadIdx.y * 32 + threadIdx.x;
    for (int idx = tid; idx < KST * NB; idx += 128)
        sKeys[idx] = (float)keys[idx];
    __syncthreads();

    const int bz = blockIdx.z;
    const int i  = blockIdx.y * 4 + threadIdx.y;
    if (i >= HO) return;
    const int j0 = blockIdx.x * 128 + threadIdx.x * 4;  // multiple of 4, <= 380

    const float* xb = x + bz * (H_IN * W_IN);

    // 3x6 patch block: float4 + predicated float2 per row; transform
    // (v - 0.5f) * pi/2 exactly as the reference; duplicate into f32x2 lanes.
    unsigned long long P[18];
    const bool tail_ok = (j0 <= W_IN - 6);   // false only for j0 == 380
    #pragma unroll
    for (int r = 0; r < 3; ++r) {
        const float* rp = xb + (i + r) * W_IN + j0;
        float4 v4 = *reinterpret_cast<const float4*>(rp);
        float2 v2 = tail_ok ? *reinterpret_cast<const float2*>(rp + 4)
                            : make_float2(0.f, 0.f);
        float v[6] = { v4.x, v4.y, v4.z, v4.w, v2.x, v2.y };
        #pragma unroll
        for (int c = 0; c < 6; ++c)
            P[r * 6 + c] = dup2((v[c] - 0.5f) * c0);
    }

    float best0 = -3.4e38f, best1 = -3.4e38f, best2 = -3.4e38f, best3 = -3.4e38f;
    int   bi0 = 0, bi1 = 0, bi2 = 0, bi3 = 0;

    #pragma unroll 16
    for (int sp = 0; sp < 32; ++sp) {
        // Warp-uniform constant loads: one 8B pair per weight row + bias.
        const unsigned long long bb = cpair(cB + 2 * sp);
        const unsigned long long w0 = cpair(cW + 0 * KST + 2 * sp);
        const unsigned long long w1 = cpair(cW + 1 * KST + 2 * sp);
        const unsigned long long w2 = cpair(cW + 2 * KST + 2 * sp);
        const unsigned long long w3 = cpair(cW + 3 * KST + 2 * sp);
        const unsigned long long w4 = cpair(cW + 4 * KST + 2 * sp);
        const unsigned long long w5 = cpair(cW + 5 * KST + 2 * sp);
        const unsigned long long w6 = cpair(cW + 6 * KST + 2 * sp);
        const unsigned long long w7 = cpair(cW + 7 * KST + 2 * sp);
        const unsigned long long w8 = cpair(cW + 8 * KST + 2 * sp);

        // Bit-identical summation order: (((p0*w0 + p1*w1) + ... ) + b)
        unsigned long long a0 = mul2(P[0], w0);
        unsigned long long a1 = mul2(P[1], w0);
        unsigned long long a2 = mul2(P[2], w0);
        unsigned long long a3 = mul2(P[3], w0);

        a0 = fma2(P[1],  w1, a0);  a1 = fma2(P[2],  w1, a1);
        a2 = fma2(P[3],  w1, a2);  a3 = fma2(P[4],  w1, a3);

        a0 = fma2(P[2],  w2, a0);  a1 = fma2(P[3],  w2, a1);
        a2 = fma2(P[4],  w2, a2);  a3 = fma2(P[5],  w2, a3);

        a0 = fma2(P[6],  w3, a0);  a1 = fma2(P[7],  w3, a1);
        a2 = fma2(P[8],  w3, a2);  a3 = fma2(P[9],  w3, a3);

        a0 = fma2(P[7],  w4, a0);  a1 = fma2(P[8],  w4, a1);
        a2 = fma2(P[9],  w4, a2);  a3 = fma2(P[10], w4, a3);

        a0 = fma2(P[8],  w5, a0);  a1 = fma2(P[9],  w5, a1);
        a2 = fma2(P[10], w5, a2);  a3 = fma2(P[11], w5, a3);

        a0 = fma2(P[12], w6, a0);  a1 = fma2(P[13], w6, a1);
        a2 = fma2(P[14], w6, a2);  a3 = fma2(P[15], w6, a3);

        a0 = fma2(P[13], w7, a0);  a1 = fma2(P[14], w7, a1);
        a2 = fma2(P[15], w7, a2);  a3 = fma2(P[16], w7, a3);

        a0 = fma2(P[14], w8, a0);  a1 = fma2(P[15], w8, a1);
        a2 = fma2(P[16], w8, a2);  a3 = fma2(P[17], w8, a3);

        a0 = add2(a0, bb);
        a1 = add2(a1, bb);
        a2 = add2(a2, bb);
        a3 = add2(a3, bb);

        // Argmax: pair winner first (independent of best), then one
        // best-dependent compare. Identical to sequential strict-> scan.
        const int s0 = sp * 2;
        float lo, hi;
        {
            unpack2(a0, lo, hi);
            const bool q = hi > lo;
            const float cand = q ? hi : lo;
            const int   ci   = q ? s0 + 1 : s0;
            if (cand > best0) { best0 = cand; bi0 = ci; }
        }
        {
            unpack2(a1, lo, hi);
            const bool q = hi > lo;
            const float cand = q ? hi : lo;
            const int   ci   = q ? s0 + 1 : s0;
            if (cand > best1) { best1 = cand; bi1 = ci; }
        }
        {
            unpack2(a2, lo, hi);
            const bool q = hi > lo;
            const float cand = q ? hi : lo;
            const int   ci   = q ? s0 + 1 : s0;
            if (cand > best2) { best2 = cand; bi2 = ci; }
        }
        {
            unpack2(a3, lo, hi);
            const bool q = hi > lo;
            const float cand = q ? hi : lo;
            const int   ci   = q ? s0 + 1 : s0;
            if (cand > best3) { best3 = cand; bi3 = ci; }
        }
    }

    // Decode + store (int32 addressing; float2 stores, 8B-aligned).
    const int obase = bz * (NB * HOWO) + i * WO + j0;
    const float* kr0 = &sKeys[bi0 * NB];
    const float* kr1 = &sKeys[bi1 * NB];
    const float* kr2 = &sKeys[bi2 * NB];
    const float* kr3 = &sKeys[bi3 * NB];
    const bool hi_ok = (j0 + 3 < WO);
    #pragma unroll
    for (int k = 0; k < NB; ++k) {
        float* op = out + obase + k * HOWO;
        *reinterpret_cast<float2*>(op) = make_float2(kr0[k], kr1[k]);
        if (hi_ok)
            *reinterpret_cast<float2*>(op + 2) = make_float2(kr2[k], kr3[k]);
    }
}

extern "C" void kernel_launch(void* const* d_in, const int* in_sizes, int n_in,
                              void* d_out, int out_size) {
    const float* x    = (const float*)d_in[0];
    const float* W    = (const float*)d_in[1];
    const float* b    = (const float*)d_in[2];
    const int*   keys = (const int*)d_in[3];
    float*       out  = (float*)d_out;

    // Device-to-device async copies into constant memory (graph-capturable).
    cudaMemcpyToSymbolAsync(cW, W, NB * KST * sizeof(float), 0,
                            cudaMemcpyDeviceToDevice);
    cudaMemcpyToSymbolAsync(cB, b, KST * sizeof(float), 0,
                            cudaMemcpyDeviceToDevice);

    dim3 block(32, 4);                 // 128 threads
    dim3 grid(3, (HO + 3) / 4, B_N);   // (3, 96, 8) = 2304 blocks
    qconv_kernel<<<grid, block>>>(x, keys, out);
}